// round 4
// baseline (speedup 1.0000x reference)
#include <cuda_runtime.h>

// ApsUp: polyphase 2x upsample + circular pad + depthwise 3x3 binomial blur,
// collapsed to a direct gather (only one of 4 phases is nonzero per batch).
//
// Shapes (fixed): inp [16,256,64,64] f32, poly [16] i32, out [16,256,128,128] f32.
//
// One block per channel (4096 blocks, 8 warps). Warp w owns input rows
// A0=8w..8w+7 -> output rows 16w..16w+15. Each lane front-loads 9 float2s
// (rows A0-r .. A0+8-r, circular) for high MLP, reuses interior rows twice
// in-register, and writes 16 float4 stores (8KB contiguous per warp).
// Horizontal circular neighbor comes from one warp shuffle per output row
// (32 lanes x 2 cols = 64 = N, so wrap == (lane +/- 1) & 31).

#define B_ 16
#define C_ 256
#define N_ 64
#define TWO_N 128

__global__ __launch_bounds__(256) void aps_up_kernel(
    const float* __restrict__ inp,
    const int*   __restrict__ poly,
    float*       __restrict__ out)
{
    const int bc = blockIdx.x;            // bb*256 + ch
    const int bb = bc >> 8;
    const int w  = threadIdx.x >> 5;
    const int L  = threadIdx.x & 31;
    const int A0 = w * 8;

    const int p = __ldg(&poly[bb]);
    const int r = p & 1;                  // row phase offset (uniform)
    const int c = p >> 1;                 // col phase offset (uniform)

    // Load 9 input rows: (A0 - r + j) mod 64, j = 0..8. float2 at col 2L.
    const float* base = inp + (size_t)bc * (N_ * N_);
    const int start = (A0 + (r ? (N_ - 1) : 0)) & (N_ - 1);

    float2 R[9];
#pragma unroll
    for (int j = 0; j < 9; ++j) {
        const int row = (start + j) & (N_ - 1);
        R[j] = *reinterpret_cast<const float2*>(base + row * N_ + 2 * L);
    }

    float* obase = out + (size_t)bc * (TWO_N * TWO_N) + 4 * L;
    const unsigned m = 0xFFFFFFFFu;

#pragma unroll
    for (int i = 0; i < 8; ++i) {
        // Input row pair for output rows 2A, 2A+1 (A = A0 + i):
        //   center = row A     = R[i + r]
        //   neigh  = row A -/+ 1 = R[i + 1 - r]
        const float2 ctr = R[i + r];
        const float2 ngb = R[i + 1 - r];

        // Vertical combine (weights folded):
        //   ve -> output row 2A + r      (0.5 * center)
        //   vo -> output row 2A + 1 - r  (0.25 * (center + neigh))
        float2 ve, vo;
        ve.x = 0.5f * ctr.x;
        ve.y = 0.5f * ctr.y;
        vo.x = 0.25f * (ctr.x + ngb.x);
        vo.y = 0.25f * (ctr.y + ngb.y);

        const int A = A0 + i;
        float* rowE = obase + (size_t)(2 * A + r)     * TWO_N;
        float* rowO = obase + (size_t)(2 * A + 1 - r) * TWO_N;

        float4 oe, oo;
        if (c == 0) {
            // need v[2L+2] = lane (L+1)'s v.x (wraps: circular)
            const float ve2 = __shfl_sync(m, ve.x, (L + 1) & 31);
            const float vo2 = __shfl_sync(m, vo.x, (L + 1) & 31);
            oe.x = 0.5f  *  ve.x;
            oe.y = 0.25f * (ve.x + ve.y);
            oe.z = 0.5f  *  ve.y;
            oe.w = 0.25f * (ve.y + ve2);
            oo.x = 0.5f  *  vo.x;
            oo.y = 0.25f * (vo.x + vo.y);
            oo.z = 0.5f  *  vo.y;
            oo.w = 0.25f * (vo.y + vo2);
        } else {
            // need v[2L-1] = lane (L-1)'s v.y (wraps: circular)
            const float vem = __shfl_sync(m, ve.y, (L + 31) & 31);
            const float vom = __shfl_sync(m, vo.y, (L + 31) & 31);
            oe.x = 0.25f * (vem + ve.x);
            oe.y = 0.5f  *  ve.x;
            oe.z = 0.25f * (ve.x + ve.y);
            oe.w = 0.5f  *  ve.y;
            oo.x = 0.25f * (vom + vo.x);
            oo.y = 0.5f  *  vo.x;
            oo.z = 0.25f * (vo.x + vo.y);
            oo.w = 0.5f  *  vo.y;
        }
        *reinterpret_cast<float4*>(rowE) = oe;
        *reinterpret_cast<float4*>(rowO) = oo;
    }
}

extern "C" void kernel_launch(void* const* d_in, const int* in_sizes, int n_in,
                              void* d_out, int out_size)
{
    const float* inp  = (const float*)d_in[0];
    const int*   poly = (const int*)d_in[1];
    float*       out  = (float*)d_out;

    aps_up_kernel<<<B_ * C_, 256>>>(inp, poly, out);
}

// round 5
// speedup vs baseline: 1.0392x; 1.0392x over previous
#include <cuda_runtime.h>

// ApsUp: polyphase 2x upsample + circular pad + depthwise 3x3 binomial blur,
// collapsed to a direct gather (only one of 4 phases is nonzero per batch).
//
// Shapes (fixed): inp [16,256,64,64] f32, poly [16] i32, out [16,256,128,128] f32.
//
// Streaming-write bound (~335 MB total traffic). Lean structure: one warp per
// (channel, input-row-pair A); lane L owns output cols 4L..4L+3 of output rows
// 2A, 2A+1. Horizontal circular neighbor via one warp shuffle per output row
// (32 lanes x 2 cols = 64 = N, so wrap == (lane +/- 1) & 31).
// Output written with __stcs (evict-first) so the 268 MB store stream doesn't
// thrash L2, keeping the 2.25x-reused input L2-resident.

#define B_ 16
#define C_ 256
#define N_ 64
#define TWO_N 128

__global__ __launch_bounds__(256) void aps_up_kernel(
    const float* __restrict__ inp,
    const int*   __restrict__ poly,
    float*       __restrict__ out)
{
    // blockIdx.x = bc*8 + g ; warp w handles row pair A = g*8 + w
    const int bc = blockIdx.x >> 3;
    const int g  = blockIdx.x & 7;
    const int w  = threadIdx.x >> 5;
    const int L  = threadIdx.x & 31;
    const int A  = g * 8 + w;
    const int bb = bc >> 8;

    const int p = __ldg(&poly[bb]);
    const int r = p & 1;                  // row phase offset (warp-uniform)
    const int c = p >> 1;                 // col phase offset (warp-uniform)

    const int a1 = (A + (r ? (N_ - 1) : 1)) & (N_ - 1);

    const float* base = inp + (size_t)bc * (N_ * N_);
    const float2 f0 = *reinterpret_cast<const float2*>(base + A  * N_ + 2 * L);
    const float2 f1 = *reinterpret_cast<const float2*>(base + a1 * N_ + 2 * L);

    // Vertical combine (weights folded in):
    //   ve -> output row 2A + r      (weight 0.5 on row A)
    //   vo -> output row 2A + 1 - r  (weight 0.25 on rows A and a1)
    float2 ve, vo;
    ve.x = 0.5f * f0.x;
    ve.y = 0.5f * f0.y;
    vo.x = 0.25f * (f0.x + f1.x);
    vo.y = 0.25f * (f0.y + f1.y);

    float* obase = out + (size_t)bc * (TWO_N * TWO_N) + 4 * L;
    float* rowE  = obase + (size_t)(2 * A + r)     * TWO_N;
    float* rowO  = obase + (size_t)(2 * A + 1 - r) * TWO_N;

    const unsigned m = 0xFFFFFFFFu;
    if (c == 0) {
        // need v[2L+2] = lane (L+1)'s v.x  (wraps to col 0 for L=31: circular)
        const float ve2 = __shfl_sync(m, ve.x, (L + 1) & 31);
        const float vo2 = __shfl_sync(m, vo.x, (L + 1) & 31);
        float4 oe, oo;
        oe.x = 0.5f  *  ve.x;
        oe.y = 0.25f * (ve.x + ve.y);
        oe.z = 0.5f  *  ve.y;
        oe.w = 0.25f * (ve.y + ve2);
        oo.x = 0.5f  *  vo.x;
        oo.y = 0.25f * (vo.x + vo.y);
        oo.z = 0.5f  *  vo.y;
        oo.w = 0.25f * (vo.y + vo2);
        __stcs(reinterpret_cast<float4*>(rowE), oe);
        __stcs(reinterpret_cast<float4*>(rowO), oo);
    } else {
        // need v[2L-1] = lane (L-1)'s v.y  (wraps to col 63 for L=0: circular)
        const float vem = __shfl_sync(m, ve.y, (L + 31) & 31);
        const float vom = __shfl_sync(m, vo.y, (L + 31) & 31);
        float4 oe, oo;
        oe.x = 0.25f * (vem + ve.x);
        oe.y = 0.5f  *  ve.x;
        oe.z = 0.25f * (ve.x + ve.y);
        oe.w = 0.5f  *  ve.y;
        oo.x = 0.25f * (vom + vo.x);
        oo.y = 0.5f  *  vo.x;
        oo.z = 0.25f * (vo.x + vo.y);
        oo.w = 0.5f  *  vo.y;
        __stcs(reinterpret_cast<float4*>(rowE), oe);
        __stcs(reinterpret_cast<float4*>(rowO), oo);
    }
}

extern "C" void kernel_launch(void* const* d_in, const int* in_sizes, int n_in,
                              void* d_out, int out_size)
{
    const float* inp  = (const float*)d_in[0];
    const int*   poly = (const int*)d_in[1];
    float*       out  = (float*)d_out;

    // 4096 channels * 8 blocks each (8 warps/block, 1 warp per row pair)
    aps_up_kernel<<<B_ * C_ * 8, 256>>>(inp, poly, out);
}

// round 6
// speedup vs baseline: 1.0417x; 1.0024x over previous
#include <cuda_runtime.h>

// ApsUp: polyphase 2x upsample + circular pad + depthwise 3x3 binomial blur,
// collapsed to a direct gather (only one of 4 phases is nonzero per batch).
//
// Shapes (fixed): inp [16,256,64,64] f32, poly [16] i32, out [16,256,128,128] f32.
//
// Memory-wall regime: 335.5 MB irreducible traffic (268.4 MB write / 67.1 MB
// read), all five prior structures converge at ~50.5us kernel (~6.6 TB/s).
// This round: lean warp-per-row-pair structure + __stwt write-through stores
// (output has zero reuse -> skip L2 allocation entirely), 512-thread blocks.
//
// Lane L owns output cols 4L..4L+3 of output rows 2A, 2A+1. Horizontal
// circular neighbor via one warp shuffle (32 lanes x 2 cols = 64 = N).

#define B_ 16
#define C_ 256
#define N_ 64
#define TWO_N 128

__global__ __launch_bounds__(512) void aps_up_kernel(
    const float* __restrict__ inp,
    const int*   __restrict__ poly,
    float*       __restrict__ out)
{
    // blockIdx.x = bc*4 + g ; warp w handles row pair A = g*16 + w
    const int bc = blockIdx.x >> 2;
    const int g  = blockIdx.x & 3;
    const int w  = threadIdx.x >> 5;
    const int L  = threadIdx.x & 31;
    const int A  = g * 16 + w;
    const int bb = bc >> 8;

    const int p = __ldg(&poly[bb]);
    const int r = p & 1;                  // row phase offset (warp-uniform)
    const int c = p >> 1;                 // col phase offset (warp-uniform)

    const int a1 = (A + (r ? (N_ - 1) : 1)) & (N_ - 1);

    const float* base = inp + (size_t)bc * (N_ * N_);
    const float2 f0 = __ldg(reinterpret_cast<const float2*>(base + A  * N_ + 2 * L));
    const float2 f1 = __ldg(reinterpret_cast<const float2*>(base + a1 * N_ + 2 * L));

    // Vertical combine (weights folded in):
    //   ve -> output row 2A + r      (weight 0.5 on row A)
    //   vo -> output row 2A + 1 - r  (weight 0.25 on rows A and a1)
    float2 ve, vo;
    ve.x = 0.5f * f0.x;
    ve.y = 0.5f * f0.y;
    vo.x = 0.25f * (f0.x + f1.x);
    vo.y = 0.25f * (f0.y + f1.y);

    float* obase = out + (size_t)bc * (TWO_N * TWO_N) + 4 * L;
    float* rowE  = obase + (size_t)(2 * A + r)     * TWO_N;
    float* rowO  = obase + (size_t)(2 * A + 1 - r) * TWO_N;

    const unsigned m = 0xFFFFFFFFu;
    if (c == 0) {
        // need v[2L+2] = lane (L+1)'s v.x  (wraps to col 0 for L=31: circular)
        const float ve2 = __shfl_sync(m, ve.x, (L + 1) & 31);
        const float vo2 = __shfl_sync(m, vo.x, (L + 1) & 31);
        float4 oe, oo;
        oe.x = 0.5f  *  ve.x;
        oe.y = 0.25f * (ve.x + ve.y);
        oe.z = 0.5f  *  ve.y;
        oe.w = 0.25f * (ve.y + ve2);
        oo.x = 0.5f  *  vo.x;
        oo.y = 0.25f * (vo.x + vo.y);
        oo.z = 0.5f  *  vo.y;
        oo.w = 0.25f * (vo.y + vo2);
        __stwt(reinterpret_cast<float4*>(rowE), oe);
        __stwt(reinterpret_cast<float4*>(rowO), oo);
    } else {
        // need v[2L-1] = lane (L-1)'s v.y  (wraps to col 63 for L=0: circular)
        const float vem = __shfl_sync(m, ve.y, (L + 31) & 31);
        const float vom = __shfl_sync(m, vo.y, (L + 31) & 31);
        float4 oe, oo;
        oe.x = 0.25f * (vem + ve.x);
        oe.y = 0.5f  *  ve.x;
        oe.z = 0.25f * (ve.x + ve.y);
        oe.w = 0.5f  *  ve.y;
        oo.x = 0.25f * (vom + vo.x);
        oo.y = 0.5f  *  vo.x;
        oo.z = 0.25f * (vo.x + vo.y);
        oo.w = 0.5f  *  vo.y;
        __stwt(reinterpret_cast<float4*>(rowE), oe);
        __stwt(reinterpret_cast<float4*>(rowO), oo);
    }
}

extern "C" void kernel_launch(void* const* d_in, const int* in_sizes, int n_in,
                              void* d_out, int out_size)
{
    const float* inp  = (const float*)d_in[0];
    const int*   poly = (const int*)d_in[1];
    float*       out  = (float*)d_out;

    // 4096 channels * 4 blocks each (16 warps/block, 1 warp per row pair)
    aps_up_kernel<<<B_ * C_ * 4, 512>>>(inp, poly, out);
}